// round 15
// baseline (speedup 1.0000x reference)
#include <cuda_runtime.h>
#include <cuda_fp16.h>
#include <cstdint>

// Problem constants
#define N_SENT 65536
#define D_DIM  2304
#define N_BAGS 4096
#define C_CLS  53
#define N_PAD  64
#define NJ     7            // n8 blocks computed (cols 0..55)
#define BM     256          // rows per CTA
#define KC     64
#define NCHUNK 36
#define KSPLIT 4
#define CHUNKS_PER_CTA (NCHUNK / KSPLIT)   // 9
#define NTHR   256
#define NMTILE (N_SENT / BM)               // 256
#define LG_STRIDE 56

typedef unsigned long long ull;

// ---------------- global scratch ----------------
__device__ __half g_BtH[N_PAD * D_DIM];
__device__ __half g_BtL[N_PAD * D_DIM];
__device__ float  g_logits[(size_t)N_SENT * LG_STRIDE];
__device__ ull    g_best[N_BAGS];

// ---------------- smem geometry (halves) ----------------
#define A_STRIDE 72
#define B_STRIDE 72
#define A_STAGE  (BM * A_STRIDE)
#define B_STAGE  (N_PAD * B_STRIDE)
#define SMEM_BYTES ((4 * A_STAGE + 4 * B_STAGE) * 2)   // 184320

// ---------------- PTX helpers ----------------
__device__ __forceinline__ void ldm4(uint32_t* r, uint32_t addr) {
    asm volatile("ldmatrix.sync.aligned.m8n8.x4.shared.b16 {%0,%1,%2,%3}, [%4];\n"
                 : "=r"(r[0]), "=r"(r[1]), "=r"(r[2]), "=r"(r[3]) : "r"(addr));
}
__device__ __forceinline__ void mma16816(float* c, const uint32_t* a,
                                         uint32_t b0, uint32_t b1) {
    asm volatile(
        "mma.sync.aligned.m16n8k16.row.col.f32.f16.f16.f32 "
        "{%0,%1,%2,%3}, {%4,%5,%6,%7}, {%8,%9}, {%0,%1,%2,%3};\n"
        : "+f"(c[0]), "+f"(c[1]), "+f"(c[2]), "+f"(c[3])
        : "r"(a[0]), "r"(a[1]), "r"(a[2]), "r"(a[3]), "r"(b0), "r"(b1));
}
__device__ __forceinline__ void cp16(uint32_t dst, const void* src) {
    asm volatile("cp.async.cg.shared.global [%0], [%1], 16;" :: "r"(dst), "l"(src));
}
#define CP_COMMIT() asm volatile("cp.async.commit_group;" ::: "memory")
#define CP_WAIT0()  asm volatile("cp.async.wait_group 0;" ::: "memory")

__device__ __forceinline__ void red2(float* p, float a, float b) {
    asm volatile("red.global.add.v2.f32 [%0], {%1, %2};" :: "l"(p), "f"(a), "f"(b) : "memory");
}

__device__ __forceinline__ void cvt_split(float4 v, uint2& hi, uint2& lo) {
    __half2 h01 = __floats2half2_rn(v.x, v.y);
    __half2 h23 = __floats2half2_rn(v.z, v.w);
    float2 f01 = __half22float2(h01);
    float2 f23 = __half22float2(h23);
    __half2 l01 = __floats2half2_rn(v.x - f01.x, v.y - f01.y);
    __half2 l23 = __floats2half2_rn(v.z - f23.x, v.w - f23.y);
    hi.x = *(uint32_t*)&h01; hi.y = *(uint32_t*)&h23;
    lo.x = *(uint32_t*)&l01; lo.y = *(uint32_t*)&l23;
}

// ---------------------------------------------------------------------------
// Kernel 1: prep W splits + zero g_logits + zero g_best (single launch)
// ---------------------------------------------------------------------------
#define ZERO4_CNT ((size_t)N_SENT * LG_STRIDE / 4)
__global__ void prep_kernel(const float* __restrict__ W) {
    size_t idx = (size_t)blockIdx.x * blockDim.x + threadIdx.x;
    if (idx < (size_t)N_PAD * D_DIM) {
        int n = (int)(idx / D_DIM);
        int k = (int)(idx - (size_t)n * D_DIM);
        float w = (n < C_CLS) ? W[n * D_DIM + k] : 0.0f;
        __half h = __float2half_rn(w);
        g_BtH[idx] = h;
        g_BtL[idx] = __float2half_rn(w - __half2float(h));
    }
    if (idx < ZERO4_CNT)
        ((float4*)g_logits)[idx] = make_float4(0.f, 0.f, 0.f, 0.f);
    if (idx < N_BAGS) g_best[idx] = 0ull;
}

// ---------------------------------------------------------------------------
// Kernel 2: split-K split-f16 GEMM — A-staging interleaved into MMA shadow
// ---------------------------------------------------------------------------
__global__ __launch_bounds__(NTHR, 1)
void main_kernel(const float* __restrict__ reps) {
    extern __shared__ __align__(16) __half sm[];
    __half* Ah = sm;
    __half* Al = sm + 2 * A_STAGE;
    __half* Bh = sm + 4 * A_STAGE;
    __half* Bl = sm + 4 * A_STAGE + 2 * B_STAGE;

    const int tid  = threadIdx.x;
    const int lane = tid & 31;
    const int wrp  = tid >> 5;
    const int mtile = blockIdx.x & (NMTILE - 1);   // kpart-major scheduling
    const int kpart = blockIdx.x >> 8;
    const int rowBase = mtile * BM;
    const int kBase = kpart * CHUNKS_PER_CTA * KC;

    const uint32_t uAh = (uint32_t)__cvta_generic_to_shared(Ah);
    const uint32_t uAl = (uint32_t)__cvta_generic_to_shared(Al);
    const uint32_t uBh = (uint32_t)__cvta_generic_to_shared(Bh);
    const uint32_t uBl = (uint32_t)__cvta_generic_to_shared(Bl);

    float acc[2][NJ][4];
    #pragma unroll
    for (int i = 0; i < 2; i++)
        #pragma unroll
        for (int j = 0; j < NJ; j++)
            #pragma unroll
            for (int q = 0; q < 4; q++) acc[i][j][q] = 0.0f;

    const int ldRow = tid >> 4;
    const int ldCol = tid & 15;
    const float* aPtr = reps + (size_t)(rowBase + ldRow) * D_DIM + ldCol * 4 + kBase;

    const int bRow = tid >> 2;
    const int bSeg = tid & 3;
    const __half* bhSrc = g_BtH + (size_t)bRow * D_DIM + kBase;
    const __half* blSrc = g_BtL + (size_t)bRow * D_DIM + kBase;
    const uint32_t bDstRow = (uint32_t)(bRow * B_STRIDE) * 2;

    int aOff[2];
    #pragma unroll
    for (int i = 0; i < 2; i++)
        aOff[i] = (wrp * 32 + i * 16 + (lane & 15)) * A_STRIDE + ((lane >> 4) << 3);
    const int bRowOff = (lane & 7) + ((lane >> 4) << 3);
    const int bColOff = ((lane >> 3) & 1) << 3;

    float4 ra[16];

    // ---- prologue ----
    #pragma unroll
    for (int i = 0; i < 2; i++) {
        int sg = bSeg + 4 * i;
        cp16(uBh + bDstRow + sg * 16, bhSrc + sg * 8);
        cp16(uBl + bDstRow + sg * 16, blSrc + sg * 8);
    }
    CP_COMMIT();
    #pragma unroll
    for (int i = 0; i < 16; i++)
        ra[i] = *(const float4*)(aPtr + (size_t)(16 * i) * D_DIM);
    #pragma unroll
    for (int i = 0; i < 16; i++) {
        uint2 hi, lo;
        cvt_split(ra[i], hi, lo);
        int off = (ldRow + 16 * i) * A_STRIDE + ldCol * 4;
        *(uint2*)(Ah + off) = hi;
        *(uint2*)(Al + off) = lo;
    }
    CP_WAIT0();
    __syncthreads();

    // ---- main loop over this CTA's 9 k-chunks ----
    for (int t = 0; t < CHUNKS_PER_CTA; t++) {
        const int buf = t & 1;
        const bool more = (t + 1 < CHUNKS_PER_CTA);

        if (more) {
            const int ko = (t + 1) * KC;
            const int nb = (t + 1) & 1;
            const uint32_t bsO = (uint32_t)(nb * B_STAGE) * 2;
            #pragma unroll
            for (int i = 0; i < 2; i++) {
                int sg = bSeg + 4 * i;
                cp16(uBh + bsO + bDstRow + sg * 16, bhSrc + ko + sg * 8);
                cp16(uBl + bsO + bDstRow + sg * 16, blSrc + ko + sg * 8);
            }
            CP_COMMIT();
            #pragma unroll
            for (int i = 0; i < 16; i++)
                ra[i] = *(const float4*)(aPtr + (size_t)(16 * i) * D_DIM + ko);
        }

        const uint32_t aStO = uint32_t(buf * A_STAGE) * 2;
        const uint32_t bStO = uint32_t(buf * B_STAGE) * 2;

        // ---- MMA k-steps s=0,1 ----
        #pragma unroll
        for (int s = 0; s < 2; s++) {
            uint32_t afh[2][4], afl[2][4];
            #pragma unroll
            for (int i = 0; i < 2; i++) {
                ldm4(afh[i], uAh + aStO + (aOff[i] + s * 16) * 2);
                ldm4(afl[i], uAl + aStO + (aOff[i] + s * 16) * 2);
            }
            uint32_t bfh[16], bfl[16];
            #pragma unroll
            for (int p = 0; p < 4; p++) {
                int boff = (16 * p + bRowOff) * B_STRIDE + s * 16 + bColOff;
                ldm4(&bfh[4 * p], uBh + bStO + boff * 2);
                ldm4(&bfl[4 * p], uBl + bStO + boff * 2);
            }
            #pragma unroll
            for (int j = 0; j < NJ; j++) {
                mma16816(acc[0][j], afh[0], bfh[2 * j], bfh[2 * j + 1]);
                mma16816(acc[1][j], afh[1], bfh[2 * j], bfh[2 * j + 1]);
            }
            #pragma unroll
            for (int j = 0; j < NJ; j++) {
                mma16816(acc[0][j], afh[0], bfl[2 * j], bfl[2 * j + 1]);
                mma16816(acc[1][j], afh[1], bfl[2 * j], bfl[2 * j + 1]);
            }
            #pragma unroll
            for (int j = 0; j < NJ; j++) {
                mma16816(acc[0][j], afl[0], bfh[2 * j], bfh[2 * j + 1]);
                mma16816(acc[1][j], afl[1], bfh[2 * j], bfh[2 * j + 1]);
            }
        }

        // ---- A convert+store for next stage, hidden in the MMA shadow.
        // Safe: the __syncthreads ending chunk t-1 guarantees no warp still
        // reads buffer nb; LDG data (issued at chunk start) has arrived.
        if (more) {
            const int nb = (t + 1) & 1;
            #pragma unroll
            for (int i = 0; i < 16; i++) {
                uint2 hi, lo;
                cvt_split(ra[i], hi, lo);
                int off = nb * A_STAGE + (ldRow + 16 * i) * A_STRIDE + ldCol * 4;
                *(uint2*)(Ah + off) = hi;
                *(uint2*)(Al + off) = lo;
            }
        }

        // ---- MMA k-steps s=2,3 ----
        #pragma unroll
        for (int s = 2; s < 4; s++) {
            uint32_t afh[2][4], afl[2][4];
            #pragma unroll
            for (int i = 0; i < 2; i++) {
                ldm4(afh[i], uAh + aStO + (aOff[i] + s * 16) * 2);
                ldm4(afl[i], uAl + aStO + (aOff[i] + s * 16) * 2);
            }
            uint32_t bfh[16], bfl[16];
            #pragma unroll
            for (int p = 0; p < 4; p++) {
                int boff = (16 * p + bRowOff) * B_STRIDE + s * 16 + bColOff;
                ldm4(&bfh[4 * p], uBh + bStO + boff * 2);
                ldm4(&bfl[4 * p], uBl + bStO + boff * 2);
            }
            #pragma unroll
            for (int j = 0; j < NJ; j++) {
                mma16816(acc[0][j], afh[0], bfh[2 * j], bfh[2 * j + 1]);
                mma16816(acc[1][j], afh[1], bfh[2 * j], bfh[2 * j + 1]);
            }
            #pragma unroll
            for (int j = 0; j < NJ; j++) {
                mma16816(acc[0][j], afh[0], bfl[2 * j], bfl[2 * j + 1]);
                mma16816(acc[1][j], afh[1], bfl[2 * j], bfl[2 * j + 1]);
            }
            #pragma unroll
            for (int j = 0; j < NJ; j++) {
                mma16816(acc[0][j], afl[0], bfh[2 * j], bfh[2 * j + 1]);
                mma16816(acc[1][j], afl[1], bfh[2 * j], bfh[2 * j + 1]);
            }
        }

        if (more) CP_WAIT0();
        __syncthreads();
    }

    // ---- epilogue: vector-reduce partial logits ----
    {
        const int cb = (lane & 3) * 2;
        #pragma unroll
        for (int i = 0; i < 2; i++) {
            const int r0 = rowBase + wrp * 32 + i * 16 + (lane >> 2);
            #pragma unroll
            for (int j = 0; j < NJ; j++) {
                int c = j * 8 + cb;
                red2(g_logits + (size_t)r0 * LG_STRIDE + c,       acc[i][j][0], acc[i][j][1]);
                red2(g_logits + (size_t)(r0 + 8) * LG_STRIDE + c, acc[i][j][2], acc[i][j][3]);
            }
        }
    }
}

// ---------------------------------------------------------------------------
// Kernel 3: argmax — CTA-staged, 128 rows/CTA, coalesced loads
// ---------------------------------------------------------------------------
#define AR_ROWS 128
#define AR_STRIDE 57
__global__ __launch_bounds__(256)
void argmax_kernel(const int* __restrict__ scope,
                   const int* __restrict__ label,
                   const float* __restrict__ bias) {
    __shared__ float lg[AR_ROWS * AR_STRIDE];
    const int tid = threadIdx.x;
    const int rowBase = blockIdx.x * AR_ROWS;

    const float4* src4 = (const float4*)(g_logits + (size_t)rowBase * LG_STRIDE);
    #pragma unroll
    for (int k = 0; k < 7; k++) {
        int idx4 = tid + k * 256;
        float4 v = src4[idx4];
        int f = idx4 * 4;
        int rr = f / LG_STRIDE;
        int cc = f - rr * LG_STRIDE;
        float* d = lg + rr * AR_STRIDE + cc;
        d[0] = v.x; d[1] = v.y; d[2] = v.z; d[3] = v.w;
    }
    __syncthreads();

    if (tid < AR_ROWS) {
        const int row = rowBase + tid;
        const float* lrow = lg + tid * AR_STRIDE;

        int lo = 0, hi = N_BAGS;
        while (hi - lo > 1) {
            int mid = (lo + hi) >> 1;
            if (scope[mid] <= row) lo = mid; else hi = mid;
        }
        const int lbl = label[lo];

        float mx = -1e30f, vlbl = 0.0f;
        #pragma unroll
        for (int c = 0; c < C_CLS; c++) {
            float v = lrow[c] + __ldg(bias + c);
            mx = fmaxf(mx, v);
            vlbl = (c == lbl) ? v : vlbl;
        }
        float ssum = 0.0f;
        #pragma unroll
        for (int c = 0; c < C_CLS; c++)
            ssum += expf(lrow[c] + __ldg(bias + c) - mx);
        const float lp = expf(vlbl - mx) * (1.0f / ssum);

        ull pk = ((ull)__float_as_uint(lp) << 32) | (unsigned)(~row);
        atomicMax(&g_best[lo], pk);
    }
}

// ---------------------------------------------------------------------------
// Kernel 4: gather — recompute softmax for the 4096 selected rows (warp/bag)
// ---------------------------------------------------------------------------
__global__ __launch_bounds__(256)
void gather_kernel(const float* __restrict__ bias, float* __restrict__ out) {
    const int gwarp = (int)((blockIdx.x * blockDim.x + threadIdx.x) >> 5);
    const int lane = threadIdx.x & 31;
    if (gwarp >= N_BAGS) return;

    const unsigned sel = ~(unsigned)g_best[gwarp];
    const float* src = g_logits + (size_t)sel * LG_STRIDE;

    const int c1 = lane + 32;
    float v0 = (lane < C_CLS) ? src[lane] + bias[lane] : -1e30f;
    float v1 = (c1 < C_CLS) ? src[c1] + bias[c1] : -1e30f;

    float mx = fmaxf(v0, v1);
    #pragma unroll
    for (int o = 16; o; o >>= 1) mx = fmaxf(mx, __shfl_xor_sync(0xffffffffu, mx, o));

    float e0 = (lane < C_CLS) ? expf(v0 - mx) : 0.0f;
    float e1 = (c1 < C_CLS) ? expf(v1 - mx) : 0.0f;
    float s = e0 + e1;
    #pragma unroll
    for (int o = 16; o; o >>= 1) s += __shfl_xor_sync(0xffffffffu, s, o);
    const float is = 1.0f / s;

    if (lane < C_CLS) out[gwarp * C_CLS + lane] = e0 * is;
    if (c1 < C_CLS)   out[gwarp * C_CLS + c1]  = e1 * is;
}

// ---------------------------------------------------------------------------
extern "C" void kernel_launch(void* const* d_in, const int* in_sizes, int n_in,
                              void* d_out, int out_size) {
    const float* reps  = (const float*)d_in[0];
    const int*   scope = (const int*)  d_in[1];
    const int*   label = (const int*)  d_in[2];
    const float* W     = (const float*)d_in[3];
    const float* b     = (const float*)d_in[4];
    float* out = (float*)d_out;

    cudaFuncSetAttribute(main_kernel,
                         cudaFuncAttributeMaxDynamicSharedMemorySize, SMEM_BYTES);

    size_t prep_items = ZERO4_CNT > (size_t)N_PAD * D_DIM ? ZERO4_CNT : (size_t)N_PAD * D_DIM;
    prep_kernel<<<(unsigned)((prep_items + 255) / 256), 256>>>(W);
    main_kernel<<<NMTILE * KSPLIT, NTHR, SMEM_BYTES>>>(reps);
    argmax_kernel<<<N_SENT / AR_ROWS, 256>>>(scope, label, b);
    gather_kernel<<<(N_BAGS * 32 + 255) / 256, 256>>>(b, out);
}

// round 16
// speedup vs baseline: 1.0113x; 1.0113x over previous
#include <cuda_runtime.h>
#include <cuda_fp16.h>
#include <cstdint>

// Problem constants
#define N_SENT 65536
#define D_DIM  2304
#define N_BAGS 4096
#define C_CLS  53
#define N_PAD  64
#define NJ     7            // n8 blocks computed (cols 0..55)
#define BM     256          // rows per CTA
#define KC     64
#define NCHUNK 36
#define KSPLIT 4
#define CHUNKS_PER_CTA (NCHUNK / KSPLIT)   // 9
#define NTHR   256
#define NMTILE (N_SENT / BM)               // 256
#define LG_STRIDE 56

typedef unsigned long long ull;

// ---------------- global scratch ----------------
__device__ __align__(16) __half g_BtH[N_PAD * D_DIM];
__device__ __align__(16) __half g_BtL[N_PAD * D_DIM];
__device__ float  g_logits[(size_t)N_SENT * LG_STRIDE];
__device__ ull    g_best[N_BAGS];

// ---------------- smem geometry (halves) ----------------
#define A_STRIDE 72
#define B_STRIDE 72
#define A_STAGE  (BM * A_STRIDE)
#define B_STAGE  (N_PAD * B_STRIDE)
#define SMEM_BYTES ((4 * A_STAGE + 4 * B_STAGE) * 2)   // 184320

// ---------------- PTX helpers ----------------
__device__ __forceinline__ void ldm4(uint32_t* r, uint32_t addr) {
    asm volatile("ldmatrix.sync.aligned.m8n8.x4.shared.b16 {%0,%1,%2,%3}, [%4];\n"
                 : "=r"(r[0]), "=r"(r[1]), "=r"(r[2]), "=r"(r[3]) : "r"(addr));
}
__device__ __forceinline__ void mma16816(float* c, const uint32_t* a,
                                         uint32_t b0, uint32_t b1) {
    asm volatile(
        "mma.sync.aligned.m16n8k16.row.col.f32.f16.f16.f32 "
        "{%0,%1,%2,%3}, {%4,%5,%6,%7}, {%8,%9}, {%0,%1,%2,%3};\n"
        : "+f"(c[0]), "+f"(c[1]), "+f"(c[2]), "+f"(c[3])
        : "r"(a[0]), "r"(a[1]), "r"(a[2]), "r"(a[3]), "r"(b0), "r"(b1));
}
__device__ __forceinline__ void cp16(uint32_t dst, const void* src) {
    asm volatile("cp.async.cg.shared.global [%0], [%1], 16;" :: "r"(dst), "l"(src));
}
#define CP_COMMIT() asm volatile("cp.async.commit_group;" ::: "memory")
#define CP_WAIT0()  asm volatile("cp.async.wait_group 0;" ::: "memory")

__device__ __forceinline__ void red2(float* p, float a, float b) {
    asm volatile("red.global.add.v2.f32 [%0], {%1, %2};" :: "l"(p), "f"(a), "f"(b) : "memory");
}

__device__ __forceinline__ void cvt_split(float4 v, uint2& hi, uint2& lo) {
    __half2 h01 = __floats2half2_rn(v.x, v.y);
    __half2 h23 = __floats2half2_rn(v.z, v.w);
    float2 f01 = __half22float2(h01);
    float2 f23 = __half22float2(h23);
    __half2 l01 = __floats2half2_rn(v.x - f01.x, v.y - f01.y);
    __half2 l23 = __floats2half2_rn(v.z - f23.x, v.w - f23.y);
    hi.x = *(uint32_t*)&h01; hi.y = *(uint32_t*)&h23;
    lo.x = *(uint32_t*)&l01; lo.y = *(uint32_t*)&l23;
}

// ---------------------------------------------------------------------------
// Kernel 1: prep W splits (vectorized 8-wide) + zero g_logits + zero g_best
// ---------------------------------------------------------------------------
#define ZERO4_CNT ((size_t)N_SENT * LG_STRIDE / 4)     // 917504 float4
#define W8_CNT    ((size_t)N_PAD * D_DIM / 8)          // 18432 threads of 8 elems
__global__ void prep_kernel(const float* __restrict__ W) {
    size_t idx = (size_t)blockIdx.x * blockDim.x + threadIdx.x;
    if (idx < W8_CNT) {
        size_t e0 = idx * 8;                 // element offset in [N_PAD][D_DIM]
        int n = (int)(e0 / D_DIM);
        int k = (int)(e0 - (size_t)n * D_DIM);   // multiple of 8 (D_DIM % 8 == 0)
        uint2 hi01, lo01, hi23, lo23;
        if (n < C_CLS) {
            const float4* wsrc = (const float4*)(W + (size_t)n * D_DIM + k);
            cvt_split(wsrc[0], hi01, lo01);
            cvt_split(wsrc[1], hi23, lo23);
        } else {
            hi01 = make_uint2(0u, 0u); lo01 = hi01;
            hi23 = hi01;               lo23 = hi01;
        }
        uint4 h4 = make_uint4(hi01.x, hi01.y, hi23.x, hi23.y);
        uint4 l4 = make_uint4(lo01.x, lo01.y, lo23.x, lo23.y);
        *(uint4*)(g_BtH + e0) = h4;
        *(uint4*)(g_BtL + e0) = l4;
    }
    if (idx < ZERO4_CNT)
        ((float4*)g_logits)[idx] = make_float4(0.f, 0.f, 0.f, 0.f);
    if (idx < N_BAGS) g_best[idx] = 0ull;
}

// ---------------------------------------------------------------------------
// Kernel 2: split-K split-f16 GEMM (r12 champion, verbatim)
// ---------------------------------------------------------------------------
__global__ __launch_bounds__(NTHR, 1)
void main_kernel(const float* __restrict__ reps) {
    extern __shared__ __align__(16) __half sm[];
    __half* Ah = sm;
    __half* Al = sm + 2 * A_STAGE;
    __half* Bh = sm + 4 * A_STAGE;
    __half* Bl = sm + 4 * A_STAGE + 2 * B_STAGE;

    const int tid  = threadIdx.x;
    const int lane = tid & 31;
    const int wrp  = tid >> 5;
    const int mtile = blockIdx.x & (NMTILE - 1);   // kpart-major scheduling
    const int kpart = blockIdx.x >> 8;
    const int rowBase = mtile * BM;
    const int kBase = kpart * CHUNKS_PER_CTA * KC;

    const uint32_t uAh = (uint32_t)__cvta_generic_to_shared(Ah);
    const uint32_t uAl = (uint32_t)__cvta_generic_to_shared(Al);
    const uint32_t uBh = (uint32_t)__cvta_generic_to_shared(Bh);
    const uint32_t uBl = (uint32_t)__cvta_generic_to_shared(Bl);

    float acc[2][NJ][4];
    #pragma unroll
    for (int i = 0; i < 2; i++)
        #pragma unroll
        for (int j = 0; j < NJ; j++)
            #pragma unroll
            for (int q = 0; q < 4; q++) acc[i][j][q] = 0.0f;

    const int ldRow = tid >> 4;
    const int ldCol = tid & 15;
    const float* aPtr = reps + (size_t)(rowBase + ldRow) * D_DIM + ldCol * 4 + kBase;

    const int bRow = tid >> 2;
    const int bSeg = tid & 3;
    const __half* bhSrc = g_BtH + (size_t)bRow * D_DIM + kBase;
    const __half* blSrc = g_BtL + (size_t)bRow * D_DIM + kBase;
    const uint32_t bDstRow = (uint32_t)(bRow * B_STRIDE) * 2;

    int aOff[2];
    #pragma unroll
    for (int i = 0; i < 2; i++)
        aOff[i] = (wrp * 32 + i * 16 + (lane & 15)) * A_STRIDE + ((lane >> 4) << 3);
    const int bRowOff = (lane & 7) + ((lane >> 4) << 3);
    const int bColOff = ((lane >> 3) & 1) << 3;

    float4 ra[16];

    // ---- prologue ----
    #pragma unroll
    for (int i = 0; i < 2; i++) {
        int sg = bSeg + 4 * i;
        cp16(uBh + bDstRow + sg * 16, bhSrc + sg * 8);
        cp16(uBl + bDstRow + sg * 16, blSrc + sg * 8);
    }
    CP_COMMIT();
    #pragma unroll
    for (int i = 0; i < 16; i++)
        ra[i] = *(const float4*)(aPtr + (size_t)(16 * i) * D_DIM);
    #pragma unroll
    for (int i = 0; i < 16; i++) {
        uint2 hi, lo;
        cvt_split(ra[i], hi, lo);
        int off = (ldRow + 16 * i) * A_STRIDE + ldCol * 4;
        *(uint2*)(Ah + off) = hi;
        *(uint2*)(Al + off) = lo;
    }
    CP_WAIT0();
    __syncthreads();

    // ---- main loop over this CTA's 9 k-chunks ----
    for (int t = 0; t < CHUNKS_PER_CTA; t++) {
        const int buf = t & 1;
        const bool more = (t + 1 < CHUNKS_PER_CTA);

        if (more) {
            const int ko = (t + 1) * KC;
            const int nb = (t + 1) & 1;
            const uint32_t bsO = (uint32_t)(nb * B_STAGE) * 2;
            #pragma unroll
            for (int i = 0; i < 2; i++) {
                int sg = bSeg + 4 * i;
                cp16(uBh + bsO + bDstRow + sg * 16, bhSrc + ko + sg * 8);
                cp16(uBl + bsO + bDstRow + sg * 16, blSrc + ko + sg * 8);
            }
            CP_COMMIT();
            #pragma unroll
            for (int i = 0; i < 16; i++)
                ra[i] = *(const float4*)(aPtr + (size_t)(16 * i) * D_DIM + ko);
        }

        const uint32_t aStO = uint32_t(buf * A_STAGE) * 2;
        const uint32_t bStO = uint32_t(buf * B_STAGE) * 2;
        #pragma unroll
        for (int s = 0; s < 4; s++) {
            uint32_t afh[2][4], afl[2][4];
            #pragma unroll
            for (int i = 0; i < 2; i++) {
                ldm4(afh[i], uAh + aStO + (aOff[i] + s * 16) * 2);
                ldm4(afl[i], uAl + aStO + (aOff[i] + s * 16) * 2);
            }
            uint32_t bfh[16], bfl[16];
            #pragma unroll
            for (int p = 0; p < 4; p++) {
                int boff = (16 * p + bRowOff) * B_STRIDE + s * 16 + bColOff;
                ldm4(&bfh[4 * p], uBh + bStO + boff * 2);
                ldm4(&bfl[4 * p], uBl + bStO + boff * 2);
            }
            #pragma unroll
            for (int j = 0; j < NJ; j++) {
                mma16816(acc[0][j], afh[0], bfh[2 * j], bfh[2 * j + 1]);
                mma16816(acc[1][j], afh[1], bfh[2 * j], bfh[2 * j + 1]);
            }
            #pragma unroll
            for (int j = 0; j < NJ; j++) {
                mma16816(acc[0][j], afh[0], bfl[2 * j], bfl[2 * j + 1]);
                mma16816(acc[1][j], afh[1], bfl[2 * j], bfl[2 * j + 1]);
            }
            #pragma unroll
            for (int j = 0; j < NJ; j++) {
                mma16816(acc[0][j], afl[0], bfh[2 * j], bfh[2 * j + 1]);
                mma16816(acc[1][j], afl[1], bfh[2 * j], bfh[2 * j + 1]);
            }
        }

        if (more) {
            const int nb = (t + 1) & 1;
            #pragma unroll
            for (int i = 0; i < 16; i++) {
                uint2 hi, lo;
                cvt_split(ra[i], hi, lo);
                int off = nb * A_STAGE + (ldRow + 16 * i) * A_STRIDE + ldCol * 4;
                *(uint2*)(Ah + off) = hi;
                *(uint2*)(Al + off) = lo;
            }
            CP_WAIT0();
        }
        __syncthreads();
    }

    // ---- epilogue: vector-reduce partial logits ----
    {
        const int cb = (lane & 3) * 2;
        #pragma unroll
        for (int i = 0; i < 2; i++) {
            const int r0 = rowBase + wrp * 32 + i * 16 + (lane >> 2);
            #pragma unroll
            for (int j = 0; j < NJ; j++) {
                int c = j * 8 + cb;
                red2(g_logits + (size_t)r0 * LG_STRIDE + c,       acc[i][j][0], acc[i][j][1]);
                red2(g_logits + (size_t)(r0 + 8) * LG_STRIDE + c, acc[i][j][2], acc[i][j][3]);
            }
        }
    }
}

// ---------------------------------------------------------------------------
// Kernel 3: argmax — CTA-staged, 128 rows/CTA, coalesced loads
// ---------------------------------------------------------------------------
#define AR_ROWS 128
#define AR_STRIDE 57
__global__ __launch_bounds__(256)
void argmax_kernel(const int* __restrict__ scope,
                   const int* __restrict__ label,
                   const float* __restrict__ bias) {
    __shared__ float lg[AR_ROWS * AR_STRIDE];
    const int tid = threadIdx.x;
    const int rowBase = blockIdx.x * AR_ROWS;

    const float4* src4 = (const float4*)(g_logits + (size_t)rowBase * LG_STRIDE);
    #pragma unroll
    for (int k = 0; k < 7; k++) {
        int idx4 = tid + k * 256;
        float4 v = src4[idx4];
        int f = idx4 * 4;
        int rr = f / LG_STRIDE;
        int cc = f - rr * LG_STRIDE;
        float* d = lg + rr * AR_STRIDE + cc;
        d[0] = v.x; d[1] = v.y; d[2] = v.z; d[3] = v.w;
    }
    __syncthreads();

    if (tid < AR_ROWS) {
        const int row = rowBase + tid;
        const float* lrow = lg + tid * AR_STRIDE;

        int lo = 0, hi = N_BAGS;
        while (hi - lo > 1) {
            int mid = (lo + hi) >> 1;
            if (scope[mid] <= row) lo = mid; else hi = mid;
        }
        const int lbl = label[lo];

        float mx = -1e30f, vlbl = 0.0f;
        #pragma unroll
        for (int c = 0; c < C_CLS; c++) {
            float v = lrow[c] + __ldg(bias + c);
            mx = fmaxf(mx, v);
            vlbl = (c == lbl) ? v : vlbl;
        }
        float ssum = 0.0f;
        #pragma unroll
        for (int c = 0; c < C_CLS; c++)
            ssum += expf(lrow[c] + __ldg(bias + c) - mx);
        const float lp = expf(vlbl - mx) * (1.0f / ssum);

        ull pk = ((ull)__float_as_uint(lp) << 32) | (unsigned)(~row);
        atomicMax(&g_best[lo], pk);
    }
}

// ---------------------------------------------------------------------------
// Kernel 4: gather — recompute softmax for the 4096 selected rows (warp/bag)
// ---------------------------------------------------------------------------
__global__ __launch_bounds__(256)
void gather_kernel(const float* __restrict__ bias, float* __restrict__ out) {
    const int gwarp = (int)((blockIdx.x * blockDim.x + threadIdx.x) >> 5);
    const int lane = threadIdx.x & 31;
    if (gwarp >= N_BAGS) return;

    const unsigned sel = ~(unsigned)g_best[gwarp];
    const float* src = g_logits + (size_t)sel * LG_STRIDE;

    const int c1 = lane + 32;
    float v0 = (lane < C_CLS) ? src[lane] + bias[lane] : -1e30f;
    float v1 = (c1 < C_CLS) ? src[c1] + bias[c1] : -1e30f;

    float mx = fmaxf(v0, v1);
    #pragma unroll
    for (int o = 16; o; o >>= 1) mx = fmaxf(mx, __shfl_xor_sync(0xffffffffu, mx, o));

    float e0 = (lane < C_CLS) ? expf(v0 - mx) : 0.0f;
    float e1 = (c1 < C_CLS) ? expf(v1 - mx) : 0.0f;
    float s = e0 + e1;
    #pragma unroll
    for (int o = 16; o; o >>= 1) s += __shfl_xor_sync(0xffffffffu, s, o);
    const float is = 1.0f / s;

    if (lane < C_CLS) out[gwarp * C_CLS + lane] = e0 * is;
    if (c1 < C_CLS)   out[gwarp * C_CLS + c1]  = e1 * is;
}

// ---------------------------------------------------------------------------
extern "C" void kernel_launch(void* const* d_in, const int* in_sizes, int n_in,
                              void* d_out, int out_size) {
    const float* reps  = (const float*)d_in[0];
    const int*   scope = (const int*)  d_in[1];
    const int*   label = (const int*)  d_in[2];
    const float* W     = (const float*)d_in[3];
    const float* b     = (const float*)d_in[4];
    float* out = (float*)d_out;

    cudaFuncSetAttribute(main_kernel,
                         cudaFuncAttributeMaxDynamicSharedMemorySize, SMEM_BYTES);

    prep_kernel<<<(unsigned)((ZERO4_CNT + 255) / 256), 256>>>(W);
    main_kernel<<<NMTILE * KSPLIT, NTHR, SMEM_BYTES>>>(reps);
    argmax_kernel<<<N_SENT / AR_ROWS, 256>>>(scope, label, b);
    gather_kernel<<<(N_BAGS * 32 + 255) / 256, 256>>>(b, out);
}

// round 17
// speedup vs baseline: 1.1059x; 1.0936x over previous
#include <cuda_runtime.h>
#include <cuda_fp16.h>
#include <cstdint>

// Problem constants
#define N_SENT 65536
#define D_DIM  2304
#define N_BAGS 4096
#define C_CLS  53
#define N_PAD  64
#define NJ     7            // n8 blocks computed (cols 0..55)
#define BM     256          // rows per tile
#define KC     64
#define NCHUNK 36
#define KSPLIT 4
#define CHUNKS_PER_CTA (NCHUNK / KSPLIT)   // 9
#define NTHR   256
#define NMTILE (N_SENT / BM)               // 256
#define NWORK  (NMTILE * KSPLIT)           // 1024 work items
#define LG_STRIDE 56

typedef unsigned long long ull;

// ---------------- global scratch ----------------
__device__ __align__(16) __half g_BtH[N_PAD * D_DIM];
__device__ __align__(16) __half g_BtL[N_PAD * D_DIM];
__device__ float  g_logits[(size_t)N_SENT * LG_STRIDE];
__device__ ull    g_best[N_BAGS];

// ---------------- smem geometry (halves) ----------------
#define A_STRIDE 72
#define B_STRIDE 72
#define A_STAGE  (BM * A_STRIDE)
#define B_STAGE  (N_PAD * B_STRIDE)
#define SMEM_BYTES ((4 * A_STAGE + 4 * B_STAGE) * 2)   // 184320

// ---------------- PTX helpers ----------------
__device__ __forceinline__ void ldm4(uint32_t* r, uint32_t addr) {
    asm volatile("ldmatrix.sync.aligned.m8n8.x4.shared.b16 {%0,%1,%2,%3}, [%4];\n"
                 : "=r"(r[0]), "=r"(r[1]), "=r"(r[2]), "=r"(r[3]) : "r"(addr));
}
__device__ __forceinline__ void mma16816(float* c, const uint32_t* a,
                                         uint32_t b0, uint32_t b1) {
    asm volatile(
        "mma.sync.aligned.m16n8k16.row.col.f32.f16.f16.f32 "
        "{%0,%1,%2,%3}, {%4,%5,%6,%7}, {%8,%9}, {%0,%1,%2,%3};\n"
        : "+f"(c[0]), "+f"(c[1]), "+f"(c[2]), "+f"(c[3])
        : "r"(a[0]), "r"(a[1]), "r"(a[2]), "r"(a[3]), "r"(b0), "r"(b1));
}
__device__ __forceinline__ void cp16(uint32_t dst, const void* src) {
    asm volatile("cp.async.cg.shared.global [%0], [%1], 16;" :: "r"(dst), "l"(src));
}
#define CP_COMMIT() asm volatile("cp.async.commit_group;" ::: "memory")
#define CP_WAIT0()  asm volatile("cp.async.wait_group 0;" ::: "memory")

__device__ __forceinline__ void red2(float* p, float a, float b) {
    asm volatile("red.global.add.v2.f32 [%0], {%1, %2};" :: "l"(p), "f"(a), "f"(b) : "memory");
}

__device__ __forceinline__ void cvt_split(float4 v, uint2& hi, uint2& lo) {
    __half2 h01 = __floats2half2_rn(v.x, v.y);
    __half2 h23 = __floats2half2_rn(v.z, v.w);
    float2 f01 = __half22float2(h01);
    float2 f23 = __half22float2(h23);
    __half2 l01 = __floats2half2_rn(v.x - f01.x, v.y - f01.y);
    __half2 l23 = __floats2half2_rn(v.z - f23.x, v.w - f23.y);
    hi.x = *(uint32_t*)&h01; hi.y = *(uint32_t*)&h23;
    lo.x = *(uint32_t*)&l01; lo.y = *(uint32_t*)&l23;
}

// ---------------------------------------------------------------------------
// Kernel 1: prep W splits (vectorized 8-wide) + zero g_logits + zero g_best
// ---------------------------------------------------------------------------
#define ZERO4_CNT ((size_t)N_SENT * LG_STRIDE / 4)
#define W8_CNT    ((size_t)N_PAD * D_DIM / 8)
__global__ void prep_kernel(const float* __restrict__ W) {
    size_t idx = (size_t)blockIdx.x * blockDim.x + threadIdx.x;
    if (idx < W8_CNT) {
        size_t e0 = idx * 8;
        int n = (int)(e0 / D_DIM);
        int k = (int)(e0 - (size_t)n * D_DIM);
        uint2 hi01, lo01, hi23, lo23;
        if (n < C_CLS) {
            const float4* wsrc = (const float4*)(W + (size_t)n * D_DIM + k);
            cvt_split(wsrc[0], hi01, lo01);
            cvt_split(wsrc[1], hi23, lo23);
        } else {
            hi01 = make_uint2(0u, 0u); lo01 = hi01;
            hi23 = hi01;               lo23 = hi01;
        }
        *(uint4*)(g_BtH + e0) = make_uint4(hi01.x, hi01.y, hi23.x, hi23.y);
        *(uint4*)(g_BtL + e0) = make_uint4(lo01.x, lo01.y, lo23.x, lo23.y);
    }
    if (idx < ZERO4_CNT)
        ((float4*)g_logits)[idx] = make_float4(0.f, 0.f, 0.f, 0.f);
    if (idx < N_BAGS) g_best[idx] = 0ull;
}

// ---------------------------------------------------------------------------
// Kernel 2: persistent split-K split-f16 GEMM with cross-tile prefetch
// ---------------------------------------------------------------------------
__global__ __launch_bounds__(NTHR, 1)
void main_kernel(const float* __restrict__ reps, int grid) {
    extern __shared__ __align__(16) __half sm[];
    __half* Ah = sm;
    __half* Al = sm + 2 * A_STAGE;
    __half* Bh = sm + 4 * A_STAGE;
    __half* Bl = sm + 4 * A_STAGE + 2 * B_STAGE;

    const int tid  = threadIdx.x;
    const int lane = tid & 31;
    const int wrp  = tid >> 5;

    const uint32_t uAh = (uint32_t)__cvta_generic_to_shared(Ah);
    const uint32_t uAl = (uint32_t)__cvta_generic_to_shared(Al);
    const uint32_t uBh = (uint32_t)__cvta_generic_to_shared(Bh);
    const uint32_t uBl = (uint32_t)__cvta_generic_to_shared(Bl);

    // thread mappings (constant across tiles)
    const int ldRow = tid >> 4;
    const int ldCol = tid & 15;
    const int bRow = tid >> 2;
    const int bSeg = tid & 3;
    const uint32_t bDstRow = (uint32_t)(bRow * B_STRIDE) * 2;

    int aOff[2];
    #pragma unroll
    for (int i = 0; i < 2; i++)
        aOff[i] = (wrp * 32 + i * 16 + (lane & 15)) * A_STRIDE + ((lane >> 4) << 3);
    const int bRowOff = (lane & 7) + ((lane >> 4) << 3);
    const int bColOff = ((lane >> 3) & 1) << 3;
    const int cb = (lane & 3) * 2;

    float acc[2][NJ][4];
    #pragma unroll
    for (int i = 0; i < 2; i++)
        #pragma unroll
        for (int j = 0; j < NJ; j++)
            #pragma unroll
            for (int q = 0; q < 4; q++) acc[i][j][q] = 0.0f;

    float4 ra[16];

    // ---- setup for first work item ----
    int w = blockIdx.x;
    int rowBase, kBase;
    {
        int mt = w & (NMTILE - 1);
        int kp = w >> 8;
        rowBase = mt * BM;
        kBase = kp * CHUNKS_PER_CTA * KC;
    }
    const float*  aCur  = reps   + (size_t)(rowBase + ldRow) * D_DIM + ldCol * 4 + kBase;
    const __half* bhCur = g_BtH + (size_t)bRow * D_DIM + kBase;
    const __half* blCur = g_BtL + (size_t)bRow * D_DIM + kBase;

    // ---- prologue: stage 0 of tile w into buffer 0 ----
    #pragma unroll
    for (int i = 0; i < 2; i++) {
        int sg = bSeg + 4 * i;
        cp16(uBh + bDstRow + sg * 16, bhCur + sg * 8);
        cp16(uBl + bDstRow + sg * 16, blCur + sg * 8);
    }
    CP_COMMIT();
    #pragma unroll
    for (int i = 0; i < 16; i++)
        ra[i] = *(const float4*)(aCur + (size_t)(16 * i) * D_DIM);
    #pragma unroll
    for (int i = 0; i < 16; i++) {
        uint2 hi, lo;
        cvt_split(ra[i], hi, lo);
        int off = (ldRow + 16 * i) * A_STRIDE + ldCol * 4;
        *(uint2*)(Ah + off) = hi;
        *(uint2*)(Al + off) = lo;
    }
    CP_WAIT0();
    __syncthreads();

    int t = 0;
    int buf = 0;

    for (;;) {
        // ---- determine and issue next stage (next chunk, or next tile's chunk 0) ----
        const float*  aNext = aCur;
        const __half* bhNext = bhCur;
        const __half* blNext = blCur;
        int rowBaseNext = rowBase;
        bool haveNext;
        int wn = w;
        const bool lastChunk = (t + 1 == CHUNKS_PER_CTA);
        if (!lastChunk) {
            haveNext = true;
            aNext  = aCur  + KC;
            bhNext = bhCur + KC;
            blNext = blCur + KC;
        } else {
            wn = w + grid;
            haveNext = (wn < NWORK);
            if (haveNext) {
                int mt = wn & (NMTILE - 1);
                int kp = wn >> 8;
                rowBaseNext = mt * BM;
                int kb = kp * CHUNKS_PER_CTA * KC;
                aNext  = reps   + (size_t)(rowBaseNext + ldRow) * D_DIM + ldCol * 4 + kb;
                bhNext = g_BtH + (size_t)bRow * D_DIM + kb;
                blNext = g_BtL + (size_t)bRow * D_DIM + kb;
            }
        }
        const int nb = buf ^ 1;
        if (haveNext) {
            const uint32_t bsO = (uint32_t)(nb * B_STAGE) * 2;
            #pragma unroll
            for (int i = 0; i < 2; i++) {
                int sg = bSeg + 4 * i;
                cp16(uBh + bsO + bDstRow + sg * 16, bhNext + sg * 8);
                cp16(uBl + bsO + bDstRow + sg * 16, blNext + sg * 8);
            }
            CP_COMMIT();
            #pragma unroll
            for (int i = 0; i < 16; i++)
                ra[i] = *(const float4*)(aNext + (size_t)(16 * i) * D_DIM);
        }

        // ---- MMA on buffer `buf` ----
        const uint32_t aStO = uint32_t(buf * A_STAGE) * 2;
        const uint32_t bStO = uint32_t(buf * B_STAGE) * 2;
        #pragma unroll
        for (int s = 0; s < 4; s++) {
            uint32_t afh[2][4], afl[2][4];
            #pragma unroll
            for (int i = 0; i < 2; i++) {
                ldm4(afh[i], uAh + aStO + (aOff[i] + s * 16) * 2);
                ldm4(afl[i], uAl + aStO + (aOff[i] + s * 16) * 2);
            }
            uint32_t bfh[16], bfl[16];
            #pragma unroll
            for (int p = 0; p < 4; p++) {
                int boff = (16 * p + bRowOff) * B_STRIDE + s * 16 + bColOff;
                ldm4(&bfh[4 * p], uBh + bStO + boff * 2);
                ldm4(&bfl[4 * p], uBl + bStO + boff * 2);
            }
            #pragma unroll
            for (int j = 0; j < NJ; j++) {
                mma16816(acc[0][j], afh[0], bfh[2 * j], bfh[2 * j + 1]);
                mma16816(acc[1][j], afh[1], bfh[2 * j], bfh[2 * j + 1]);
            }
            #pragma unroll
            for (int j = 0; j < NJ; j++) {
                mma16816(acc[0][j], afh[0], bfl[2 * j], bfl[2 * j + 1]);
                mma16816(acc[1][j], afh[1], bfl[2 * j], bfl[2 * j + 1]);
            }
            #pragma unroll
            for (int j = 0; j < NJ; j++) {
                mma16816(acc[0][j], afl[0], bfh[2 * j], bfh[2 * j + 1]);
                mma16816(acc[1][j], afl[1], bfh[2 * j], bfh[2 * j + 1]);
            }
        }

        if (haveNext) {
            #pragma unroll
            for (int i = 0; i < 16; i++) {
                uint2 hi, lo;
                cvt_split(ra[i], hi, lo);
                int off = nb * A_STAGE + (ldRow + 16 * i) * A_STRIDE + ldCol * 4;
                *(uint2*)(Ah + off) = hi;
                *(uint2*)(Al + off) = lo;
            }
            CP_WAIT0();
        }

        // ---- tile epilogue: drain accumulators before the boundary sync ----
        if (lastChunk) {
            #pragma unroll
            for (int i = 0; i < 2; i++) {
                const int r0 = rowBase + wrp * 32 + i * 16 + (lane >> 2);
                #pragma unroll
                for (int j = 0; j < NJ; j++) {
                    int c = j * 8 + cb;
                    red2(g_logits + (size_t)r0 * LG_STRIDE + c,       acc[i][j][0], acc[i][j][1]);
                    red2(g_logits + (size_t)(r0 + 8) * LG_STRIDE + c, acc[i][j][2], acc[i][j][3]);
                }
            }
            #pragma unroll
            for (int i = 0; i < 2; i++)
                #pragma unroll
                for (int j = 0; j < NJ; j++)
                    #pragma unroll
                    for (int q = 0; q < 4; q++) acc[i][j][q] = 0.0f;
        }

        __syncthreads();

        if (!lastChunk) {
            t++;
        } else {
            if (!haveNext) break;
            w = wn;
            t = 0;
            rowBase = rowBaseNext;
        }
        aCur = aNext; bhCur = bhNext; blCur = blNext;
        buf = nb;
    }
}

// ---------------------------------------------------------------------------
// Kernel 3: argmax — CTA-staged, 128 rows/CTA, coalesced loads
// ---------------------------------------------------------------------------
#define AR_ROWS 128
#define AR_STRIDE 57
__global__ __launch_bounds__(256)
void argmax_kernel(const int* __restrict__ scope,
                   const int* __restrict__ label,
                   const float* __restrict__ bias) {
    __shared__ float lg[AR_ROWS * AR_STRIDE];
    const int tid = threadIdx.x;
    const int rowBase = blockIdx.x * AR_ROWS;

    const float4* src4 = (const float4*)(g_logits + (size_t)rowBase * LG_STRIDE);
    #pragma unroll
    for (int k = 0; k < 7; k++) {
        int idx4 = tid + k * 256;
        float4 v = src4[idx4];
        int f = idx4 * 4;
        int rr = f / LG_STRIDE;
        int cc = f - rr * LG_STRIDE;
        float* d = lg + rr * AR_STRIDE + cc;
        d[0] = v.x; d[1] = v.y; d[2] = v.z; d[3] = v.w;
    }
    __syncthreads();

    if (tid < AR_ROWS) {
        const int row = rowBase + tid;
        const float* lrow = lg + tid * AR_STRIDE;

        int lo = 0, hi = N_BAGS;
        while (hi - lo > 1) {
            int mid = (lo + hi) >> 1;
            if (scope[mid] <= row) lo = mid; else hi = mid;
        }
        const int lbl = label[lo];

        float mx = -1e30f, vlbl = 0.0f;
        #pragma unroll
        for (int c = 0; c < C_CLS; c++) {
            float v = lrow[c] + __ldg(bias + c);
            mx = fmaxf(mx, v);
            vlbl = (c == lbl) ? v : vlbl;
        }
        float ssum = 0.0f;
        #pragma unroll
        for (int c = 0; c < C_CLS; c++)
            ssum += expf(lrow[c] + __ldg(bias + c) - mx);
        const float lp = expf(vlbl - mx) * (1.0f / ssum);

        ull pk = ((ull)__float_as_uint(lp) << 32) | (unsigned)(~row);
        atomicMax(&g_best[lo], pk);
    }
}

// ---------------------------------------------------------------------------
// Kernel 4: gather — recompute softmax for the 4096 selected rows (warp/bag)
// ---------------------------------------------------------------------------
__global__ __launch_bounds__(256)
void gather_kernel(const float* __restrict__ bias, float* __restrict__ out) {
    const int gwarp = (int)((blockIdx.x * blockDim.x + threadIdx.x) >> 5);
    const int lane = threadIdx.x & 31;
    if (gwarp >= N_BAGS) return;

    const unsigned sel = ~(unsigned)g_best[gwarp];
    const float* src = g_logits + (size_t)sel * LG_STRIDE;

    const int c1 = lane + 32;
    float v0 = (lane < C_CLS) ? src[lane] + bias[lane] : -1e30f;
    float v1 = (c1 < C_CLS) ? src[c1] + bias[c1] : -1e30f;

    float mx = fmaxf(v0, v1);
    #pragma unroll
    for (int o = 16; o; o >>= 1) mx = fmaxf(mx, __shfl_xor_sync(0xffffffffu, mx, o));

    float e0 = (lane < C_CLS) ? expf(v0 - mx) : 0.0f;
    float e1 = (c1 < C_CLS) ? expf(v1 - mx) : 0.0f;
    float s = e0 + e1;
    #pragma unroll
    for (int o = 16; o; o >>= 1) s += __shfl_xor_sync(0xffffffffu, s, o);
    const float is = 1.0f / s;

    if (lane < C_CLS) out[gwarp * C_CLS + lane] = e0 * is;
    if (c1 < C_CLS)   out[gwarp * C_CLS + c1]  = e1 * is;
}

// ---------------------------------------------------------------------------
extern "C" void kernel_launch(void* const* d_in, const int* in_sizes, int n_in,
                              void* d_out, int out_size) {
    const float* reps  = (const float*)d_in[0];
    const int*   scope = (const int*)  d_in[1];
    const int*   label = (const int*)  d_in[2];
    const float* W     = (const float*)d_in[3];
    const float* b     = (const float*)d_in[4];
    float* out = (float*)d_out;

    cudaFuncSetAttribute(main_kernel,
                         cudaFuncAttributeMaxDynamicSharedMemorySize, SMEM_BYTES);

    int sms = 148;
    cudaDeviceGetAttribute(&sms, cudaDevAttrMultiProcessorCount, 0);
    int grid = sms < NWORK ? sms : NWORK;

    prep_kernel<<<(unsigned)((ZERO4_CNT + 255) / 256), 256>>>(W);
    main_kernel<<<grid, NTHR, SMEM_BYTES>>>(reps, grid);
    argmax_kernel<<<N_SENT / AR_ROWS, 256>>>(scope, label, b);
    gather_kernel<<<(N_BAGS * 32 + 255) / 256, 256>>>(b, out);
}